// round 4
// baseline (speedup 1.0000x reference)
#include <cuda_runtime.h>
#include <cuda_bf16.h>
#include <cstdint>
#include <math.h>

#define T_STEPS 2048
#define B_ROWS  64
#define TNO     501
#define NBASIS  30
#define RD      16      // pipeline ring depth (power of 2)
#define RDM     15
#define NEAR    8       // delays 1..8 handled in decision-thread registers
#define ACC_N   512     // far-delay accumulator ring (power of 2 > TNO)
#define ACC_M   511
#define NTH     128

// ---------------------------------------------------------------------------
// Threefry-2x32, 20 rounds — bit-exact port of jax/_src/prng.py threefry2x32
// ---------------------------------------------------------------------------
__device__ __forceinline__ void tf2x32(uint32_t k0, uint32_t k1,
                                       uint32_t x0, uint32_t x1,
                                       uint32_t &o0, uint32_t &o1) {
    uint32_t k2 = k0 ^ k1 ^ 0x1BD11BDAu;
#define TFR(r) { x0 += x1; x1 = __funnelshift_l(x1, x1, (r)); x1 ^= x0; }
    x0 += k0; x1 += k1;
    TFR(13) TFR(15) TFR(26) TFR(6)
    x0 += k1; x1 += k2 + 1u;
    TFR(17) TFR(29) TFR(16) TFR(24)
    x0 += k2; x1 += k0 + 2u;
    TFR(13) TFR(15) TFR(26) TFR(6)
    x0 += k0; x1 += k1 + 3u;
    TFR(17) TFR(29) TFR(16) TFR(24)
    x0 += k1; x1 += k2 + 4u;
    TFR(13) TFR(15) TFR(26) TFR(6)
    x0 += k2; x1 += k0 + 5u;
#undef TFR
    o0 = x0; o1 = x1;
}

// XLA ElementalIrEmitter::EmitTanh — Eigen rational, clamp [-9,9],
// |x| < 0.0004 -> x.  Mul/add kept UNcontracted to match XLA HLO emission.
__device__ __forceinline__ float tanh_xla(float x) {
    float ax = fabsf(x);
    float xc = fminf(fmaxf(x, -9.0f), 9.0f);
    float x2 = __fmul_rn(xc, xc);
    float num = -2.76076847742355e-16f;
    num = __fadd_rn(__fmul_rn(x2, num),  2.00018790482477e-13f);
    num = __fadd_rn(__fmul_rn(x2, num), -8.60467152213735e-11f);
    num = __fadd_rn(__fmul_rn(x2, num),  5.12229709037114e-08f);
    num = __fadd_rn(__fmul_rn(x2, num),  1.48572235717979e-05f);
    num = __fadd_rn(__fmul_rn(x2, num),  6.37261928875436e-04f);
    num = __fadd_rn(__fmul_rn(x2, num),  4.89352455891786e-03f);
    num = __fmul_rn(xc, num);
    float den = 1.19825839466702e-06f;
    den = __fadd_rn(__fmul_rn(x2, den),  1.18534705686654e-04f);
    den = __fadd_rn(__fmul_rn(x2, den),  2.26843463243900e-03f);
    den = __fadd_rn(__fmul_rn(x2, den),  4.89352518554385e-03f);
    float r = __fdiv_rn(num, den);
    return (ax < 0.0004f) ? x : r;
}

// intra-CTA acquire/release on shared-memory flags
__device__ __forceinline__ int ld_acq(int *p) {
    int v;
    uint32_t a = (uint32_t)__cvta_generic_to_shared(p);
    asm volatile("ld.acquire.cta.shared.b32 %0, [%1];" : "=r"(v) : "r"(a) : "memory");
    return v;
}
__device__ __forceinline__ void st_rel(int *p, int v) {
    uint32_t a = (uint32_t)__cvta_generic_to_shared(p);
    asm volatile("st.release.cta.shared.b32 [%0], %1;" :: "r"(a), "r"(v) : "memory");
}

// ---------------------------------------------------------------------------
// One block per row b.  Warp-specialized pipeline:
//   tid 0  : key-split chain (serial threefry chain — global critical path)
//   tid 32 : per-row uniform producer tf(sub_t, (0,b))
//   tid 64 : decision (sigmoid + Bernoulli compare + outputs; near delays 1..8)
//   tid 96+: scatter warp (far delays 9..501 into acc ring)
// ---------------------------------------------------------------------------
__global__ __launch_bounds__(NTH)
void apnn_kernel(const float *__restrict__ V,  const float *__restrict__ D,
                 const float *__restrict__ w1, const float *__restrict__ b1,
                 const float *__restrict__ w2, const float *__restrict__ b2,
                 const float *__restrict__ Wref, float *__restrict__ out) {
    __shared__ float    acc[ACC_N];       // pending far refract contributions
    __shared__ float    wdel[TNO];        // wdel[j] = weight for delay j+1
    __shared__ float    nnrow[T_STEPS];   // pointwise MLP output, this row
    __shared__ uint32_t subring[RD][2];
    __shared__ float    uring[RD];
    __shared__ float    spikering[RD];
    __shared__ int      chain_seq, u_seq, dec_seq, scatter_seq;

    const int tid = threadIdx.x;
    const int b   = blockIdx.x;

    // ---------------- init ----------------
    for (int i = tid; i < ACC_N; i += NTH) acc[i] = 0.0f;
    if (tid == 0) { chain_seq = 0; u_seq = 0; dec_seq = 0; scatter_seq = 0; }

    // refractory delay weights: wdel[j] = sum_i f32(basis_f64[i,j]) * Wref[i]
    // basis replicated in float64 exactly as the numpy reference.
    for (int j = tid; j < TNO; j += NTH) {
        double raw = 7.5 * log(((double)j + 1.0) + 1e-7);   // (x+SHIFT)+1e-7
        double cr = cos(raw), sr = sin(raw);
        float s = 0.0f;
        #pragma unroll 1
        for (int i = 0; i < NBASIS; i++) {
            double phi = 1.5707963267948966 * (double)i;    // (0.5*np.pi)*i
            float bas = 0.0f;
            if (!(raw < phi - 3.141592653589793 || raw > phi + 3.141592653589793)) {
                double cv;                                   // cos(raw - i*pi/2)
                switch (i & 3) {
                    case 0:  cv =  cr; break;
                    case 1:  cv =  sr; break;
                    case 2:  cv = -cr; break;
                    default: cv = -sr; break;
                }
                bas = (float)(0.5 * cv + 0.5);
            }
            s = __fmaf_rn(bas, Wref[i], s);
        }
        wdel[j] = s;
    }

    // pointwise MLP: nn[t] = sum_h w2[h]*tanh(w1[h,0]*V + w1[h,1]*D + b1[h]) + b2
    {
        float a0 = w1[0], a1 = w1[1], a2 = w1[2], a3 = w1[3], a4 = w1[4];
        float a5 = w1[5], a6 = w1[6], a7 = w1[7], a8 = w1[8], a9 = w1[9];
        float c0 = b1[0], c1 = b1[1], c2 = b1[2], c3 = b1[3], c4 = b1[4];
        float v0 = w2[0], v1 = w2[1], v2 = w2[2], v3 = w2[3], v4 = w2[4];
        float bb = b2[0];
        const float *Vr = V + (size_t)b * T_STEPS;
        const float *Dr = D + (size_t)b * T_STEPS;
        for (int t = tid; t < T_STEPS; t += NTH) {
            float vv = Vr[t], dd = Dr[t];
            float h0 = tanh_xla(__fadd_rn(__fadd_rn(__fmul_rn(a0, vv), __fmul_rn(a1, dd)), c0));
            float h1 = tanh_xla(__fadd_rn(__fadd_rn(__fmul_rn(a2, vv), __fmul_rn(a3, dd)), c1));
            float h2 = tanh_xla(__fadd_rn(__fadd_rn(__fmul_rn(a4, vv), __fmul_rn(a5, dd)), c2));
            float h3 = tanh_xla(__fadd_rn(__fadd_rn(__fmul_rn(a6, vv), __fmul_rn(a7, dd)), c3));
            float h4 = tanh_xla(__fadd_rn(__fadd_rn(__fmul_rn(a8, vv), __fmul_rn(a9, dd)), c4));
            float s = __fmul_rn(v0, h0);
            s = __fadd_rn(s, __fmul_rn(v1, h1));
            s = __fadd_rn(s, __fmul_rn(v2, h2));
            s = __fadd_rn(s, __fmul_rn(v3, h3));
            s = __fadd_rn(s, __fmul_rn(v4, h4));
            nnrow[t] = __fadd_rn(s, bb);
        }
    }
    __syncthreads();

    // ---------------- role dispatch (each role owns a whole warp slot) -------
    if (tid == 0) {
        // serial split chain: new_key = tf(key,(0,0)); sub = tf(key,(0,1))
        uint32_t k0 = 0u, k1 = 42u;               // jax.random.key(42) -> (0,42)
        int us = 0;
        for (int t = 0; t < T_STEPS; t++) {
            if (us < t - RD + 1) {                // slot t&15 free once u_seq>=t-15
                do { us = ld_acq(&u_seq); } while (us < t - RD + 1);
            }
            uint32_t nk0, nk1, s0, s1;
            tf2x32(k0, k1, 0u, 0u, nk0, nk1);
            tf2x32(k0, k1, 0u, 1u, s0, s1);
            subring[t & RDM][0] = s0;
            subring[t & RDM][1] = s1;
            st_rel(&chain_seq, t + 1);
            k0 = nk0; k1 = nk1;
        }
    } else if (tid == 32) {
        // uniform producer: bits = y0 ^ y1 of tf(sub_t, (0, b))
        int cs = 0, ds = 0;
        do { cs = ld_acq(&chain_seq); } while (cs < 1);
        uint32_t s0 = subring[0][0], s1 = subring[0][1];
        for (int t = 0; t < T_STEPS; t++) {
            // opportunistic prefetch of next sub (hides LDS under the tf)
            uint32_t n0 = 0, n1 = 0;
            bool have = (t + 1 < T_STEPS) && (cs >= t + 2);
            if (have) { n0 = subring[(t + 1) & RDM][0]; n1 = subring[(t + 1) & RDM][1]; }
            uint32_t y0, y1;
            tf2x32(s0, s1, 0u, (uint32_t)b, y0, y1);
            uint32_t bits = y0 ^ y1;
            float u = __uint_as_float((bits >> 9) | 0x3F800000u) - 1.0f;
            if (ds < t - RD + 1) {                // uring slot free once dec_seq>=t-15
                do { ds = ld_acq(&dec_seq); } while (ds < t - RD + 1);
            }
            uring[t & RDM] = u;
            st_rel(&u_seq, t + 1);
            if (t + 1 < T_STEPS) {
                if (!have) {
                    if (cs < t + 2) { do { cs = ld_acq(&chain_seq); } while (cs < t + 2); }
                    n0 = subring[(t + 1) & RDM][0]; n1 = subring[(t + 1) & RDM][1];
                }
                s0 = n0; s1 = n1;
            }
        }
    } else if (tid == 64) {
        // decision: P = 0.5*tanh(0.5*(nn+refract))+0.5 ; spike = (u < P)
        float f1 = 0.f, f2 = 0.f, f3 = 0.f, f4 = 0.f,
              f5 = 0.f, f6 = 0.f, f7 = 0.f, f8 = 0.f;   // near-delay pipeline
        const float wd0 = wdel[0], wd1 = wdel[1], wd2 = wdel[2], wd3 = wdel[3];
        const float wd4 = wdel[4], wd5 = wdel[5], wd6 = wdel[6], wd7 = wdel[7];
        float *Sout = out + (size_t)b * T_STEPS;
        float *Pout = out + (size_t)B_ROWS * T_STEPS + (size_t)b * T_STEPS;
        int us = 0, ss = 0;
        for (int t = 0; t < T_STEPS; t++) {
            if (us < t + 1) { do { us = ld_acq(&u_seq); } while (us < t + 1); }
            float u = uring[t & RDM];
            if (ss < t - NEAR) {                  // spikes <= t-9 applied to acc
                do { ss = ld_acq(&scatter_seq); } while (ss < t - NEAR);
            }
            int slot = t & ACC_M;
            float far = acc[slot];
            acc[slot] = 0.0f;                      // recycle for step t+512
            float rf = __fadd_rn(far, f1);
            float x  = __fadd_rn(nnrow[t], rf);
            float P  = __fadd_rn(__fmul_rn(0.5f, tanh_xla(__fmul_rn(0.5f, x))), 0.5f);
            float spike = (u < P) ? 1.0f : 0.0f;
            Sout[t] = spike;
            Pout[t] = P;
            spikering[t & RDM] = spike;
            st_rel(&dec_seq, t + 1);
            // shift near-delay registers
            f1 = __fmaf_rn(wd0, spike, f2);
            f2 = __fmaf_rn(wd1, spike, f3);
            f3 = __fmaf_rn(wd2, spike, f4);
            f4 = __fmaf_rn(wd3, spike, f5);
            f5 = __fmaf_rn(wd4, spike, f6);
            f6 = __fmaf_rn(wd5, spike, f7);
            f7 = __fmaf_rn(wd6, spike, f8);
            f8 = __fmul_rn(wd7, spike);
        }
    } else if (tid >= 96) {
        // scatter warp: far delays d = 9..501 into acc ring
        const int lane = tid - 96;
        int ds = 0;
        for (int t = 0; t < T_STEPS; t++) {
            if (ds < t + 1) { do { ds = ld_acq(&dec_seq); } while (ds < t + 1); }
            float spike = spikering[t & RDM];
            if (spike != 0.0f) {
                #pragma unroll 4
                for (int d = NEAR + 1 + lane; d <= TNO; d += 32) {
                    int sl = (t + d) & ACC_M;      // conflict-free: consecutive lanes
                    acc[sl] = __fadd_rn(acc[sl], wdel[d - 1]);
                }
            }
            __syncwarp();
            if (lane == 0) st_rel(&scatter_seq, t + 1);
        }
    }
}

extern "C" void kernel_launch(void* const* d_in, const int* in_sizes, int n_in,
                              void* d_out, int out_size) {
    const float *V    = (const float*)d_in[0];
    const float *D    = (const float*)d_in[1];
    const float *w1   = (const float*)d_in[2];
    const float *b1   = (const float*)d_in[3];
    const float *w2   = (const float*)d_in[4];
    const float *b2   = (const float*)d_in[5];
    const float *Wref = (const float*)d_in[6];
    float *out = (float*)d_out;
    apnn_kernel<<<B_ROWS, NTH>>>(V, D, w1, b1, w2, b2, Wref, out);
}

// round 5
// speedup vs baseline: 1.0023x; 1.0023x over previous
#include <cuda_runtime.h>
#include <cuda_bf16.h>
#include <cstdint>
#include <math.h>

#define T_STEPS 2048
#define B_ROWS  64
#define TNO     501
#define NBASIS  30
#define NEAR    12      // delays 1..12 in decision-thread registers
#define ACC_N   512     // far-delay accumulator ring (power of 2 > TNO)
#define ACC_M   511
#define NTH     128

// ---------------------------------------------------------------------------
// Threefry-2x32, 20 rounds — bit-exact port of jax/_src/prng.py threefry2x32
// ---------------------------------------------------------------------------
__device__ __forceinline__ void tf2x32(uint32_t k0, uint32_t k1,
                                       uint32_t x0, uint32_t x1,
                                       uint32_t &o0, uint32_t &o1) {
    uint32_t k2 = k0 ^ k1 ^ 0x1BD11BDAu;
#define TFR(r) { x0 += x1; x1 = __funnelshift_l(x1, x1, (r)); x1 ^= x0; }
    x0 += k0; x1 += k1;
    TFR(13) TFR(15) TFR(26) TFR(6)
    x0 += k1; x1 += k2 + 1u;
    TFR(17) TFR(29) TFR(16) TFR(24)
    x0 += k2; x1 += k0 + 2u;
    TFR(13) TFR(15) TFR(26) TFR(6)
    x0 += k0; x1 += k1 + 3u;
    TFR(17) TFR(29) TFR(16) TFR(24)
    x0 += k1; x1 += k2 + 4u;
    TFR(13) TFR(15) TFR(26) TFR(6)
    x0 += k2; x1 += k0 + 5u;
#undef TFR
    o0 = x0; o1 = x1;
}

// XLA ElementalIrEmitter::EmitTanh — Eigen rational, clamp [-9,9],
// |x| < 0.0004 -> x.  Mul/add kept UNcontracted to match XLA HLO emission.
// (This exact form produced rel_err 8e-8 — zero Bernoulli flips. DO NOT TOUCH.)
__device__ __forceinline__ float tanh_xla(float x) {
    float ax = fabsf(x);
    float xc = fminf(fmaxf(x, -9.0f), 9.0f);
    float x2 = __fmul_rn(xc, xc);
    float num = -2.76076847742355e-16f;
    num = __fadd_rn(__fmul_rn(x2, num),  2.00018790482477e-13f);
    num = __fadd_rn(__fmul_rn(x2, num), -8.60467152213735e-11f);
    num = __fadd_rn(__fmul_rn(x2, num),  5.12229709037114e-08f);
    num = __fadd_rn(__fmul_rn(x2, num),  1.48572235717979e-05f);
    num = __fadd_rn(__fmul_rn(x2, num),  6.37261928875436e-04f);
    num = __fadd_rn(__fmul_rn(x2, num),  4.89352455891786e-03f);
    num = __fmul_rn(xc, num);
    float den = 1.19825839466702e-06f;
    den = __fadd_rn(__fmul_rn(x2, den),  1.18534705686654e-04f);
    den = __fadd_rn(__fmul_rn(x2, den),  2.26843463243900e-03f);
    den = __fadd_rn(__fmul_rn(x2, den),  4.89352518554385e-03f);
    float r = __fdiv_rn(num, den);
    return (ax < 0.0004f) ? x : r;
}

// producer-side release (orders preceding smem stores before the flag)
__device__ __forceinline__ void st_rel(int *p, int v) {
    uint32_t a = (uint32_t)__cvta_generic_to_shared(p);
    asm volatile("st.release.cta.shared.b32 [%0], %1;" :: "r"(a), "r"(v) : "memory");
}
// consumer-side plain volatile poll (cheap LDS; per-warp in-order LSU makes
// subsequent data loads safe once the flag is observed)
__device__ __forceinline__ int ldv(volatile int *p) { return *p; }

// ---------------------------------------------------------------------------
// One block per row b.  Warp-specialized free-running pipeline (full-size
// rings => no backpressure; the only serial couplings are the key chain and
// the spike->refract->P->spike recurrence):
//   warp0/lane0 : key-split chain (serial threefry chain)
//   warp1/lane0 : per-row uniform producer tf(sub_t, (0,b))
//   warp2/lane0 : decision (sigmoid + Bernoulli compare + outputs; delays 1..12)
//   warp3       : scatter (far delays 13..501 into acc ring)
// ---------------------------------------------------------------------------
__global__ __launch_bounds__(NTH)
void apnn_kernel(const float *__restrict__ V,  const float *__restrict__ D,
                 const float *__restrict__ w1, const float *__restrict__ b1,
                 const float *__restrict__ w2, const float *__restrict__ b2,
                 const float *__restrict__ Wref, float *__restrict__ out) {
    __shared__ float    nnrow[T_STEPS];        // MLP output, this row      8 KB
    __shared__ uint32_t subring[T_STEPS][2];   // per-step subkeys         16 KB
    __shared__ float    uring[T_STEPS];        // per-step uniforms          8 KB
    __shared__ float    spikering[T_STEPS];    // spikes                     8 KB
    __shared__ float    acc[ACC_N];            // pending far refract        2 KB
    __shared__ float    wdel[TNO];             // wdel[j] = weight, delay j+1
    __shared__ int      chain_seq, u_seq, dec_seq, scatter_seq;

    const int tid = threadIdx.x;
    const int b   = blockIdx.x;

    // ---------------- init ----------------
    for (int i = tid; i < ACC_N; i += NTH) acc[i] = 0.0f;
    if (tid == 0) { chain_seq = 0; u_seq = 0; dec_seq = 0; scatter_seq = 0; }

    // refractory delay weights: wdel[j] = sum_i f32(basis_f64[i,j]) * Wref[i]
    for (int j = tid; j < TNO; j += NTH) {
        double raw = 7.5 * log(((double)j + 1.0) + 1e-7);
        double cr = cos(raw), sr = sin(raw);
        float s = 0.0f;
        #pragma unroll 1
        for (int i = 0; i < NBASIS; i++) {
            double phi = 1.5707963267948966 * (double)i;
            float bas = 0.0f;
            if (!(raw < phi - 3.141592653589793 || raw > phi + 3.141592653589793)) {
                double cv;
                switch (i & 3) {
                    case 0:  cv =  cr; break;
                    case 1:  cv =  sr; break;
                    case 2:  cv = -cr; break;
                    default: cv = -sr; break;
                }
                bas = (float)(0.5 * cv + 0.5);
            }
            s = __fmaf_rn(bas, Wref[i], s);
        }
        wdel[j] = s;
    }

    // pointwise MLP
    {
        float a0 = w1[0], a1 = w1[1], a2 = w1[2], a3 = w1[3], a4 = w1[4];
        float a5 = w1[5], a6 = w1[6], a7 = w1[7], a8 = w1[8], a9 = w1[9];
        float c0 = b1[0], c1 = b1[1], c2 = b1[2], c3 = b1[3], c4 = b1[4];
        float v0 = w2[0], v1 = w2[1], v2 = w2[2], v3 = w2[3], v4 = w2[4];
        float bb = b2[0];
        const float *Vr = V + (size_t)b * T_STEPS;
        const float *Dr = D + (size_t)b * T_STEPS;
        for (int t = tid; t < T_STEPS; t += NTH) {
            float vv = Vr[t], dd = Dr[t];
            float h0 = tanh_xla(__fadd_rn(__fadd_rn(__fmul_rn(a0, vv), __fmul_rn(a1, dd)), c0));
            float h1 = tanh_xla(__fadd_rn(__fadd_rn(__fmul_rn(a2, vv), __fmul_rn(a3, dd)), c1));
            float h2 = tanh_xla(__fadd_rn(__fadd_rn(__fmul_rn(a4, vv), __fmul_rn(a5, dd)), c2));
            float h3 = tanh_xla(__fadd_rn(__fadd_rn(__fmul_rn(a6, vv), __fmul_rn(a7, dd)), c3));
            float h4 = tanh_xla(__fadd_rn(__fadd_rn(__fmul_rn(a8, vv), __fmul_rn(a9, dd)), c4));
            float s = __fmul_rn(v0, h0);
            s = __fadd_rn(s, __fmul_rn(v1, h1));
            s = __fadd_rn(s, __fmul_rn(v2, h2));
            s = __fadd_rn(s, __fmul_rn(v3, h3));
            s = __fadd_rn(s, __fmul_rn(v4, h4));
            nnrow[t] = __fadd_rn(s, bb);
        }
    }
    __syncthreads();

    // ---------------- role dispatch ----------------
    if (tid == 0) {
        // serial split chain: new_key = tf(key,(0,0)); sub = tf(key,(0,1))
        // Free-running (full ring, no backpressure); flag batched every 4.
        uint32_t k0 = 0u, k1 = 42u;               // jax.random.key(42) -> (0,42)
        for (int t = 0; t < T_STEPS; t++) {
            uint32_t nk0, nk1, s0, s1;
            tf2x32(k0, k1, 0u, 0u, nk0, nk1);
            tf2x32(k0, k1, 0u, 1u, s0, s1);
            subring[t][0] = s0;
            subring[t][1] = s1;
            if ((t & 3) == 3) st_rel(&chain_seq, t + 1);
            k0 = nk0; k1 = nk1;
        }
    } else if (tid == 32) {
        // uniform producer: bits = y0 ^ y1 of tf(sub_t, (0,b))
        int cs = 0;
        for (int t = 0; t < T_STEPS; t++) {
            if (cs < t + 1) { do { cs = ldv(&chain_seq); } while (cs < t + 1); }
            uint32_t s0 = subring[t][0];
            uint32_t s1 = subring[t][1];
            uint32_t y0, y1;
            tf2x32(s0, s1, 0u, (uint32_t)b, y0, y1);
            uint32_t bits = y0 ^ y1;
            uring[t] = __uint_as_float((bits >> 9) | 0x3F800000u) - 1.0f;
            st_rel(&u_seq, t + 1);
        }
    } else if (tid == 64) {
        // decision: P = 0.5*tanh(0.5*(nn+refract))+0.5 ; spike = (u < P)
        float f1 = 0.f, f2 = 0.f, f3 = 0.f, f4 = 0.f, f5 = 0.f, f6 = 0.f,
              f7 = 0.f, f8 = 0.f, f9 = 0.f, f10 = 0.f, f11 = 0.f, f12 = 0.f;
        const float wd0 = wdel[0],  wd1 = wdel[1],  wd2 = wdel[2],  wd3 = wdel[3];
        const float wd4 = wdel[4],  wd5 = wdel[5],  wd6 = wdel[6],  wd7 = wdel[7];
        const float wd8 = wdel[8],  wd9 = wdel[9],  wd10 = wdel[10], wd11 = wdel[11];
        float *Sout = out + (size_t)b * T_STEPS;
        float *Pout = out + (size_t)B_ROWS * T_STEPS + (size_t)b * T_STEPS;
        int us = 0, ss = 0;
        float nn_cur = nnrow[0];
        for (int t = 0; t < T_STEPS; t++) {
            // far-accumulator gate: writes to slot t are from spikes <= t-13,
            // covered once scatter_seq >= t-12 (scatter flag lags <=1 batched).
            if (ss < t - NEAR) { do { ss = ldv(&scatter_seq); } while (ss < t - NEAR); }
            int slot = t & ACC_M;
            float far = acc[slot];
            acc[slot] = 0.0f;                      // recycle for step t+512
            float rf = __fadd_rn(far, f1);
            float x  = __fadd_rn(nn_cur, rf);
            float P  = __fadd_rn(__fmul_rn(0.5f, tanh_xla(__fmul_rn(0.5f, x))), 0.5f);
            // poll u AFTER issuing the sigmoid chain so the wait hides under it
            if (us < t + 1) { do { us = ldv(&u_seq); } while (us < t + 1); }
            float u = uring[t];
            float spike = (u < P) ? 1.0f : 0.0f;
            Sout[t] = spike;
            Pout[t] = P;
            spikering[t] = spike;
            st_rel(&dec_seq, t + 1);
            if (t + 1 < T_STEPS) nn_cur = nnrow[t + 1];   // prefetch
            // shift near-delay registers (delays 1..12)
            f1  = __fmaf_rn(wd0,  spike, f2);
            f2  = __fmaf_rn(wd1,  spike, f3);
            f3  = __fmaf_rn(wd2,  spike, f4);
            f4  = __fmaf_rn(wd3,  spike, f5);
            f5  = __fmaf_rn(wd4,  spike, f6);
            f6  = __fmaf_rn(wd5,  spike, f7);
            f7  = __fmaf_rn(wd6,  spike, f8);
            f8  = __fmaf_rn(wd7,  spike, f9);
            f9  = __fmaf_rn(wd8,  spike, f10);
            f10 = __fmaf_rn(wd9,  spike, f11);
            f11 = __fmaf_rn(wd10, spike, f12);
            f12 = __fmul_rn(wd11, spike);
        }
    } else if (tid >= 96) {
        // scatter warp: far delays d = 13..501 into acc ring
        const int lane = tid - 96;
        int ds = 0;
        for (int t = 0; t < T_STEPS; t++) {
            if (ds < t + 1) { do { ds = ldv(&dec_seq); } while (ds < t + 1); }
            float spike = spikering[t];
            if (spike != 0.0f) {
                #pragma unroll 4
                for (int d = NEAR + 1 + lane; d <= TNO; d += 32) {
                    int sl = (t + d) & ACC_M;      // conflict-free: consecutive lanes
                    acc[sl] = __fadd_rn(acc[sl], wdel[d - 1]);
                }
            }
            __syncwarp();                          // all lanes' STS visible
            if (lane == 0 && (t & 1)) st_rel(&scatter_seq, t + 1);
        }
        // final release so nothing is left unpublished
        if (lane == 0) st_rel(&scatter_seq, T_STEPS);
    }
}

extern "C" void kernel_launch(void* const* d_in, const int* in_sizes, int n_in,
                              void* d_out, int out_size) {
    const float *V    = (const float*)d_in[0];
    const float *D    = (const float*)d_in[1];
    const float *w1   = (const float*)d_in[2];
    const float *b1   = (const float*)d_in[3];
    const float *w2   = (const float*)d_in[4];
    const float *b2   = (const float*)d_in[5];
    const float *Wref = (const float*)d_in[6];
    float *out = (float*)d_out;
    apnn_kernel<<<B_ROWS, NTH>>>(V, D, w1, b1, w2, b2, Wref, out);
}